// round 15
// baseline (speedup 1.0000x reference)
#include <cuda_runtime.h>
#include <cuda_fp16.h>
#include <cstdint>

#define NS   524288
#define DIM  128
#define BG   128
#define HH   64
#define KK_  4
#define BH   (BG * HH)
#define NK   (NS * KK_)
#define HUBF_ELEMS (BH * DIM)

#define TILES_PER_HALF 2
#define FFN_GRID (NS / 256)     /* 2048 */

// FFN output scratch (fp16)
__device__ __half g_hbufh[(size_t)NS * DIM];
// knn table: [B*H][4]
__device__ int g_knn[BH * KK_];

// Prepped fp16 weights, transposed [n][k], XOR-swizzled
__device__ __half gW1[256 * 128];
__device__ __half gW2[128 * 256];

// SMEM layout (ffn): 224KB
#define OFF_W1  0
#define OFF_W2  65536
#define OFF_X   131072     /* per-half: +half*16384 */
#define OFF_H1  163840     /* per-half: +half*32768 */
#define FFN_SMEM 229376

// ---------------------------------------------------------------------------
__device__ __forceinline__ uint32_t smem_u32(const void* p) {
    uint32_t a;
    asm("{ .reg .u64 t; cvta.to.shared.u64 t, %1; cvt.u32.u64 %0, t; }" : "=r"(a) : "l"(p));
    return a;
}
__device__ __forceinline__ void ldsm4(uint32_t addr, uint32_t r[4]) {
    asm volatile("ldmatrix.sync.aligned.m8n8.x4.shared.b16 {%0,%1,%2,%3}, [%4];"
                 : "=r"(r[0]), "=r"(r[1]), "=r"(r[2]), "=r"(r[3]) : "r"(addr));
}
__device__ __forceinline__ void mma16816(float c[4], const uint32_t a[4], uint32_t b0, uint32_t b1) {
    asm volatile("mma.sync.aligned.m16n8k16.row.col.f32.f16.f16.f32 "
                 "{%0,%1,%2,%3}, {%4,%5,%6,%7}, {%8,%9}, {%0,%1,%2,%3};"
                 : "+f"(c[0]), "+f"(c[1]), "+f"(c[2]), "+f"(c[3])
                 : "r"(a[0]), "r"(a[1]), "r"(a[2]), "r"(a[3]), "r"(b0), "r"(b1));
}
__device__ __forceinline__ uint32_t a_addr(uint32_t base, int stride, int m0, int kb, int lane) {
    int row = m0 + (lane & 15);
    int k = kb + ((lane >> 4) << 4);
    return base + row * stride + (uint32_t)(k ^ ((row & 7) << 4));
}
__device__ __forceinline__ uint32_t b_addr(uint32_t base, int stride, int n0, int kb, int lane) {
    int row = n0 + (lane & 7) + ((lane & 16) >> 1);
    int k = kb + (((lane >> 3) & 1) << 4);
    return base + row * stride + (uint32_t)(k ^ ((row & 7) << 4));
}
__device__ __forceinline__ float gelu_fast(float v) {
    float c = v * fmaf(v * v, 0.044715f, 1.0f) * 0.7978845608f;
    float t;
    asm("tanh.approx.f32 %0, %1;" : "=f"(t) : "f"(c));
    return 0.5f * v * (1.0f + t);
}
__device__ __forceinline__ uint32_t pack_h2(__half a, __half b) {
    __half2 t; t.x = a; t.y = b;
    return *(uint32_t*)&t;
}
#define HBAR(id) asm volatile("bar.sync %0, 256;" :: "r"(id) : "memory")

// ---------------------------------------------------------------------------
// K0: weight prep
// ---------------------------------------------------------------------------
__global__ void prep_weights(const float* __restrict__ W1, const float* __restrict__ W2) {
    int tid = threadIdx.x + blockIdx.x * blockDim.x;
    int stride = blockDim.x * gridDim.x;
    for (int i = tid; i < 32768; i += stride) {
        int n = i >> 7, k = i & 127;
        uint32_t off = (uint32_t)(n * 256) + (uint32_t)((k * 2) ^ ((n & 7) << 4));
        *(__half*)((char*)gW1 + off) = __float2half_rn(W1[k * 256 + n]);
    }
    for (int i = tid; i < 32768; i += stride) {
        int n = i >> 8, k = i & 255;
        uint32_t off = (uint32_t)(n * 512) + (uint32_t)((k * 2) ^ ((n & 7) << 4));
        *(__half*)((char*)gW2 + off) = __float2half_rn(W2[k * 128 + n]);
    }
}

__global__ void nudge_kernel() {}

// ---------------------------------------------------------------------------
// K1: FFN, phase-shifted halves (frozen — 289us measured)
// ---------------------------------------------------------------------------
__global__ void __launch_bounds__(512)
ffn_mma(const float* __restrict__ x,
        const float* __restrict__ b1, const float* __restrict__ b2) {
    extern __shared__ char sm[];
    const uint32_t sb = smem_u32(sm);
    const int tid = threadIdx.x;
    const int wid = tid >> 5;
    const int lane = tid & 31;
    const int half = wid >> 3;
    const int tid_h = tid & 255;
    const int hw = wid & 7;
    const int wm = hw & 1;
    const int wn = hw >> 1;

    const uint32_t offX  = OFF_X  + (uint32_t)half * 16384;
    const uint32_t offH1 = OFF_H1 + (uint32_t)half * 32768;
    const int bar = 1 + half;

    {
        const uint4* s1 = (const uint4*)gW1;
        const uint4* s2 = (const uint4*)gW2;
        uint4* d1 = (uint4*)(sm + OFF_W1);
        uint4* d2 = (uint4*)(sm + OFF_W2);
#pragma unroll 4
        for (int i = tid; i < 4096; i += 512) { d1[i] = s1[i]; d2[i] = s2[i]; }
    }
    __syncthreads();

    for (int t = 0; t < TILES_PER_HALF; t++) {
        const size_t rowbase =
            (size_t)(blockIdx.x * (2 * TILES_PER_HALF) + half * TILES_PER_HALF + t) * 64;

        {
            const float4* xg = (const float4*)(x + rowbase * DIM);
#pragma unroll
            for (int ii = 0; ii < 8; ii++) {
                int i = tid_h + ii * 256;
                float4 v = xg[i];
                int row = i >> 5, k = (i & 31) * 4;
                uint32_t off = (uint32_t)((k * 2) ^ ((row & 7) << 4)) + row * 256;
                *(uint2*)(sm + offX + off) =
                    make_uint2(pack_h2(__float2half_rn(v.x), __float2half_rn(v.y)),
                               pack_h2(__float2half_rn(v.z), __float2half_rn(v.w)));
            }
        }
        HBAR(bar);

        float acc[2][8][4];
#pragma unroll
        for (int a = 0; a < 2; a++)
#pragma unroll
            for (int b = 0; b < 8; b++)
#pragma unroll
                for (int c = 0; c < 4; c++) acc[a][b][c] = 0.f;

#pragma unroll
        for (int ks = 0; ks < 8; ks++) {
            const int kb = ks * 32;
            uint32_t aw[2][4];
#pragma unroll
            for (int mt = 0; mt < 2; mt++)
                ldsm4(a_addr(sb + offX, 256, wm * 32 + mt * 16, kb, lane), aw[mt]);
#pragma unroll
            for (int ntp = 0; ntp < 4; ntp++) {
                const int n0 = wn * 64 + ntp * 16;
                uint32_t bw[4];
                ldsm4(b_addr(sb + OFF_W1, 256, n0, kb, lane), bw);
#pragma unroll
                for (int mt = 0; mt < 2; mt++) {
                    mma16816(acc[mt][ntp * 2],     aw[mt], bw[0], bw[1]);
                    mma16816(acc[mt][ntp * 2 + 1], aw[mt], bw[2], bw[3]);
                }
            }
        }

#pragma unroll
        for (int nt = 0; nt < 8; nt++) {
            const int col = wn * 64 + nt * 8 + (lane & 3) * 2;
            const float2 bb = *(const float2*)&b1[col];
#pragma unroll
            for (int mt = 0; mt < 2; mt++) {
                const int r = wm * 32 + mt * 16 + (lane >> 2);
#pragma unroll
                for (int h = 0; h < 2; h++) {
                    const int rr = r + h * 8;
                    float v0 = gelu_fast(acc[mt][nt][h * 2]     + bb.x);
                    float v1 = gelu_fast(acc[mt][nt][h * 2 + 1] + bb.y);
                    uint32_t off = rr * 512 + (uint32_t)((col * 2) ^ ((rr & 7) << 4));
                    *(uint32_t*)(sm + offH1 + off) =
                        pack_h2(__float2half_rn(v0), __float2half_rn(v1));
                }
            }
        }
        HBAR(bar);

        float acc2[2][4][4];
#pragma unroll
        for (int a = 0; a < 2; a++)
#pragma unroll
            for (int b = 0; b < 4; b++)
#pragma unroll
                for (int c = 0; c < 4; c++) acc2[a][b][c] = 0.f;

#pragma unroll
        for (int ks = 0; ks < 16; ks++) {
            const int kb = ks * 32;
            uint32_t aw[2][4];
#pragma unroll
            for (int mt = 0; mt < 2; mt++)
                ldsm4(a_addr(sb + offH1, 512, wm * 32 + mt * 16, kb, lane), aw[mt]);
#pragma unroll
            for (int ntp = 0; ntp < 2; ntp++) {
                const int n0 = wn * 32 + ntp * 16;
                uint32_t bw[4];
                ldsm4(b_addr(sb + OFF_W2, 512, n0, kb, lane), bw);
#pragma unroll
                for (int mt = 0; mt < 2; mt++) {
                    mma16816(acc2[mt][ntp * 2],     aw[mt], bw[0], bw[1]);
                    mma16816(acc2[mt][ntp * 2 + 1], aw[mt], bw[2], bw[3]);
                }
            }
        }

#pragma unroll
        for (int nt = 0; nt < 4; nt++) {
            const int col = wn * 32 + nt * 8 + (lane & 3) * 2;
            const float2 bb = *(const float2*)&b2[col];
#pragma unroll
            for (int mt = 0; mt < 2; mt++) {
                const int r = wm * 32 + mt * 16 + (lane >> 2);
#pragma unroll
                for (int h = 0; h < 2; h++) {
                    const int rr = r + h * 8;
                    *(uint32_t*)&g_hbufh[(rowbase + rr) * DIM + col] =
                        pack_h2(__float2half_rn(acc2[mt][nt][h * 2] + bb.x),
                                __float2half_rn(acc2[mt][nt][h * 2 + 1] + bb.y));
                }
            }
        }
        HBAR(bar);
    }
}

// ---------------------------------------------------------------------------
// K2: scatter-mean v5. Gather with uint4 (16B) loads: thread = (hub, row-group,
// 16B-segment); 4 rows in flight per hub, unroll 4 -> 16 outstanding 16B loads
// per thread-group. Fixed-order cross-group reduction (deterministic).
// ---------------------------------------------------------------------------
#define SPLITS 16
#define WLMAX  96
#define CLMAX  768

__global__ void __launch_bounds__(256)
scatter_gather(const int* __restrict__ hub_idx,
               const int* __restrict__ batch_idx,
               float* __restrict__ hubf_out) {
    __shared__ int wlist[8][4][WLMAX];
    __shared__ int wcnt[8][4];
    __shared__ int clist[4][CLMAX];
    __shared__ int ccnt[4];
    __shared__ int coff[8][4];
    __shared__ int srange[2];
    __shared__ float sred[4][4][128];   // [hub][row-group][dim] 8KB

    const int b = blockIdx.x >> 4;
    const int p = blockIdx.x & 15;
    const int h0 = p * 4;
    const int tid = threadIdx.x;
    const int w = tid >> 5;
    const int lane = tid & 31;

    if (lane < 4) wcnt[w][lane] = 0;
    if (tid < 2) {
        int target = b + tid, lo = 0, hi = NS;
        while (lo < hi) { int mid = (lo + hi) >> 1; if (batch_idx[mid] < target) lo = mid + 1; else hi = mid; }
        srange[tid] = lo;
    }
    __syncthreads();

    const int s0 = srange[0];
    const int n = srange[1] - s0;
    const int chunk = (n + 7) >> 3;
    const int cs = s0 + w * chunk;
    const int ce = min(cs + chunk, s0 + n);

    // phase 1: per-warp parallel list build
    const unsigned lt = (1u << lane) - 1u;
    for (int base = cs; base < ce; base += 32) {
        int i = base + lane;
        int h = (i < ce) ? __ldg(&hub_idx[i]) : -1;
        int hl = h - h0;
        bool in = (hl >= 0) && (hl < 4);
        unsigned mm = __match_any_sync(0xffffffffu, h);
        if (in) {
            int rank = __popc(mm & lt);
            int cnt = __popc(mm);
            int basec = wcnt[w][hl];
            wlist[w][hl][basec + rank] = i;
            if (rank == cnt - 1) wcnt[w][hl] = basec + cnt;
        }
        __syncwarp();
    }
    __syncthreads();

    // phase 2: compact
    if (tid < 4) {
        int run = 0;
#pragma unroll
        for (int ww = 0; ww < 8; ww++) { coff[ww][tid] = run; run += wcnt[ww][tid]; }
        ccnt[tid] = run;
    }
    __syncthreads();
#pragma unroll
    for (int hl = 0; hl < 4; hl++) {
        int c = wcnt[w][hl], o = coff[w][hl];
        for (int j = lane; j < c; j += 32) clist[hl][o + j] = wlist[w][hl][j];
    }
    __syncthreads();

    // phase 3: wide gather. thread = (hub hl, row-group rg, segment seg)
    {
        const int hl = tid >> 6;            // 0..3
        const int t = tid & 63;
        const int rg = t >> 4;              // 0..3
        const int seg = t & 15;             // dims seg*8 .. seg*8+7
        const int cnt = ccnt[hl];
        const int* lst = clist[hl];

        float s[8];
#pragma unroll
        for (int q = 0; q < 8; q++) s[q] = 0.f;

        int j = rg;
        for (; j + 12 < cnt; j += 16) {     // 4 rows of this group in flight
            uint4 u0 = *(const uint4*)&g_hbufh[(size_t)lst[j]      * DIM + seg * 8];
            uint4 u1 = *(const uint4*)&g_hbufh[(size_t)lst[j + 4]  * DIM + seg * 8];
            uint4 u2 = *(const uint4*)&g_hbufh[(size_t)lst[j + 8]  * DIM + seg * 8];
            uint4 u3 = *(const uint4*)&g_hbufh[(size_t)lst[j + 12] * DIM + seg * 8];
            const uint32_t* pu[4] = { &u0.x, &u1.x, &u2.x, &u3.x };
#pragma unroll
            for (int r = 0; r < 4; r++)
#pragma unroll
                for (int q = 0; q < 4; q++) {
                    float2 f = __half22float2(*(const __half2*)&pu[r][q]);
                    s[q * 2] += f.x; s[q * 2 + 1] += f.y;
                }
        }
        for (; j < cnt; j += 4) {
            uint4 u = *(const uint4*)&g_hbufh[(size_t)lst[j] * DIM + seg * 8];
            const uint32_t* pu = &u.x;
#pragma unroll
            for (int q = 0; q < 4; q++) {
                float2 f = __half22float2(*(const __half2*)&pu[q]);
                s[q * 2] += f.x; s[q * 2 + 1] += f.y;
            }
        }
#pragma unroll
        for (int q = 0; q < 8; q++) sred[hl][rg][seg * 8 + q] = s[q];
    }
    __syncthreads();

    // final: 256 threads cover 4 hubs x 128 dims / 2; fixed-order rg sum
    for (int o = tid; o < 4 * 128; o += 256) {
        const int hl = o >> 7;
        const int d = o & 127;
        float sum = sred[hl][0][d] + sred[hl][1][d] + sred[hl][2][d] + sred[hl][3][d];
        hubf_out[((size_t)b * HH + h0 + hl) * DIM + d] = sum / (float)max(ccnt[hl], 1);
    }
}

// ---------------------------------------------------------------------------
// K3a: kNN, 2 blocks per graph (32 i-rows each) -> g_knn
// ---------------------------------------------------------------------------
__global__ void __launch_bounds__(256)
knn_kernel(const float* __restrict__ hubf) {
    __shared__ float hf[HH][DIM + 1];
    __shared__ float d2row[8][HH];

    const int b = blockIdx.x >> 1;
    const int hp = blockIdx.x & 1;
    const int tid = threadIdx.x;
    const int warp = tid >> 5, lane = tid & 31;

    for (int i = tid; i < HH * DIM; i += 256) {
        int h = i >> 7, d = i & 127;
        hf[h][d] = hubf[((size_t)b * HH + h) * DIM + d];
    }
    __syncthreads();

    for (int i = hp * 32 + warp; i < hp * 32 + 32; i += 8) {
        for (int jj = 0; jj < HH; jj += 32) {
            int j = jj + lane;
            float s = 0.f;
#pragma unroll
            for (int d = 0; d < DIM; d++) {
                float diff = hf[i][d] - hf[j][d];
                s = fmaf(diff, diff, s);
            }
            d2row[warp][j] = s;
        }
        float v0 = d2row[warp][lane], v1 = d2row[warp][lane + 32];
        int   i0 = lane,              i1 = lane + 32;
#pragma unroll
        for (int k = 0; k < KK_; k++) {
            float bv; int bi;
            if (v0 < v1 || (v0 == v1 && i0 < i1)) { bv = v0; bi = i0; }
            else                                   { bv = v1; bi = i1; }
#pragma unroll
            for (int off = 16; off; off >>= 1) {
                float ov = __shfl_xor_sync(0xffffffffu, bv, off);
                int   oi = __shfl_xor_sync(0xffffffffu, bi, off);
                if (ov < bv || (ov == bv && oi < bi)) { bv = ov; bi = oi; }
            }
            if (lane == 0) g_knn[(b * HH + i) * KK_ + k] = bi;
            if (i0 == bi) v0 = 3.4e38f;
            if (i1 == bi) v1 = 3.4e38f;
        }
    }
}

// ---------------------------------------------------------------------------
// K3b: edge emit — 4 spokes per thread, batched loads (MLP 4)
// ---------------------------------------------------------------------------
__global__ void __launch_bounds__(512)
edge_kernel(const int* __restrict__ hub_idx,
            const int* __restrict__ batch_idx,
            float* __restrict__ e0, float* __restrict__ e1) {
    const int base = blockIdx.x * 2048 + threadIdx.x;
    int sb4[4], sh4[4];
#pragma unroll
    for (int k = 0; k < 4; k++) {
        int s = base + k * 512;
        sb4[k] = __ldg(&batch_idx[s]);
        sh4[k] = __ldg(&hub_idx[s]);
    }
    int4 kn4[4];
#pragma unroll
    for (int k = 0; k < 4; k++)
        kn4[k] = *(const int4*)&g_knn[(sb4[k] * HH + sh4[k]) * KK_];
#pragma unroll
    for (int k = 0; k < 4; k++) {
        int s = base + k * 512;
        const float fs = (float)s;
        const float boff = (float)(sb4[k] * HH);
        *(float4*)&e0[(size_t)s * 4] = make_float4(fs, fs, fs, fs);
        *(float4*)&e1[(size_t)s * 4] =
            make_float4(kn4[k].x + boff, kn4[k].y + boff, kn4[k].z + boff, kn4[k].w + boff);
    }
}

// ---------------------------------------------------------------------------
extern "C" void kernel_launch(void* const* d_in, const int* in_sizes, int n_in,
                              void* d_out, int out_size) {
    const float* x   = (const float*)d_in[0];
    const int*   hub = (const int*)d_in[1];
    const int*   bix = (const int*)d_in[2];
    const float* W1  = (const float*)d_in[3];
    const float* b1  = (const float*)d_in[4];
    const float* W2  = (const float*)d_in[5];
    const float* b2  = (const float*)d_in[6];

    float* out  = (float*)d_out;
    float* hubf = out;
    float* e0   = out + HUBF_ELEMS;
    float* e1   = out + HUBF_ELEMS + NK;

    cudaFuncSetAttribute(ffn_mma, cudaFuncAttributeMaxDynamicSharedMemorySize, FFN_SMEM);

    prep_weights<<<64, 256>>>(W1, W2);                     // idx 0
    nudge_kernel<<<1, 32>>>();                              // idx 1
    ffn_mma<<<FFN_GRID, 512, FFN_SMEM>>>(x, b1, b2);       // idx 2
    scatter_gather<<<BG * SPLITS, 256>>>(hub, bix, hubf);  // idx 3 <- ncu
    knn_kernel<<<BG * 2, 256>>>(hubf);
    edge_kernel<<<NS / 2048, 512>>>(hub, bix, e0, e1);
}

// round 16
// speedup vs baseline: 1.0456x; 1.0456x over previous
#include <cuda_runtime.h>
#include <cuda_fp16.h>
#include <cstdint>

#define NS   524288
#define DIM  128
#define BG   128
#define HH   64
#define KK_  4
#define BH   (BG * HH)
#define NK   (NS * KK_)
#define HUBF_ELEMS (BH * DIM)

#define TILES_PER_HALF 2
#define FFN_GRID (NS / 256)     /* 2048 */

// FFN output scratch (fp16)
__device__ __half g_hbufh[(size_t)NS * DIM];
// knn table: [B*H][4]
__device__ int g_knn[BH * KK_];

// Prepped fp16 weights, transposed [n][k], XOR-swizzled
__device__ __half gW1[256 * 128];
__device__ __half gW2[128 * 256];

// SMEM layout (ffn): 224KB
#define OFF_W1  0
#define OFF_W2  65536
#define OFF_X   131072     /* per-half: +half*16384 */
#define OFF_H1  163840     /* per-half: +half*32768 */
#define FFN_SMEM 229376

// ---------------------------------------------------------------------------
__device__ __forceinline__ uint32_t smem_u32(const void* p) {
    uint32_t a;
    asm("{ .reg .u64 t; cvta.to.shared.u64 t, %1; cvt.u32.u64 %0, t; }" : "=r"(a) : "l"(p));
    return a;
}
__device__ __forceinline__ void ldsm4(uint32_t addr, uint32_t r[4]) {
    asm volatile("ldmatrix.sync.aligned.m8n8.x4.shared.b16 {%0,%1,%2,%3}, [%4];"
                 : "=r"(r[0]), "=r"(r[1]), "=r"(r[2]), "=r"(r[3]) : "r"(addr));
}
__device__ __forceinline__ void mma16816(float c[4], const uint32_t a[4], uint32_t b0, uint32_t b1) {
    asm volatile("mma.sync.aligned.m16n8k16.row.col.f32.f16.f16.f32 "
                 "{%0,%1,%2,%3}, {%4,%5,%6,%7}, {%8,%9}, {%0,%1,%2,%3};"
                 : "+f"(c[0]), "+f"(c[1]), "+f"(c[2]), "+f"(c[3])
                 : "r"(a[0]), "r"(a[1]), "r"(a[2]), "r"(a[3]), "r"(b0), "r"(b1));
}
__device__ __forceinline__ uint32_t a_addr(uint32_t base, int stride, int m0, int kb, int lane) {
    int row = m0 + (lane & 15);
    int k = kb + ((lane >> 4) << 4);
    return base + row * stride + (uint32_t)(k ^ ((row & 7) << 4));
}
__device__ __forceinline__ uint32_t b_addr(uint32_t base, int stride, int n0, int kb, int lane) {
    int row = n0 + (lane & 7) + ((lane & 16) >> 1);
    int k = kb + (((lane >> 3) & 1) << 4);
    return base + row * stride + (uint32_t)(k ^ ((row & 7) << 4));
}
__device__ __forceinline__ float gelu_fast(float v) {
    float c = v * fmaf(v * v, 0.044715f, 1.0f) * 0.7978845608f;
    float t;
    asm("tanh.approx.f32 %0, %1;" : "=f"(t) : "f"(c));
    return 0.5f * v * (1.0f + t);
}
__device__ __forceinline__ uint32_t pack_h2(__half a, __half b) {
    __half2 t; t.x = a; t.y = b;
    return *(uint32_t*)&t;
}
#define HBAR(id) asm volatile("bar.sync %0, 256;" :: "r"(id) : "memory")

// ---------------------------------------------------------------------------
// K0: weight prep
// ---------------------------------------------------------------------------
__global__ void prep_weights(const float* __restrict__ W1, const float* __restrict__ W2) {
    int tid = threadIdx.x + blockIdx.x * blockDim.x;
    int stride = blockDim.x * gridDim.x;
    for (int i = tid; i < 32768; i += stride) {
        int n = i >> 7, k = i & 127;
        uint32_t off = (uint32_t)(n * 256) + (uint32_t)((k * 2) ^ ((n & 7) << 4));
        *(__half*)((char*)gW1 + off) = __float2half_rn(W1[k * 256 + n]);
    }
    for (int i = tid; i < 32768; i += stride) {
        int n = i >> 8, k = i & 255;
        uint32_t off = (uint32_t)(n * 512) + (uint32_t)((k * 2) ^ ((n & 7) << 4));
        *(__half*)((char*)gW2 + off) = __float2half_rn(W2[k * 128 + n]);
    }
}

__global__ void nudge_kernel() {}

// ---------------------------------------------------------------------------
// K1: FFN, phase-shifted halves (frozen — 289us measured)
// ---------------------------------------------------------------------------
__global__ void __launch_bounds__(512)
ffn_mma(const float* __restrict__ x,
        const float* __restrict__ b1, const float* __restrict__ b2) {
    extern __shared__ char sm[];
    const uint32_t sb = smem_u32(sm);
    const int tid = threadIdx.x;
    const int wid = tid >> 5;
    const int lane = tid & 31;
    const int half = wid >> 3;
    const int tid_h = tid & 255;
    const int hw = wid & 7;
    const int wm = hw & 1;
    const int wn = hw >> 1;

    const uint32_t offX  = OFF_X  + (uint32_t)half * 16384;
    const uint32_t offH1 = OFF_H1 + (uint32_t)half * 32768;
    const int bar = 1 + half;

    {
        const uint4* s1 = (const uint4*)gW1;
        const uint4* s2 = (const uint4*)gW2;
        uint4* d1 = (uint4*)(sm + OFF_W1);
        uint4* d2 = (uint4*)(sm + OFF_W2);
#pragma unroll 4
        for (int i = tid; i < 4096; i += 512) { d1[i] = s1[i]; d2[i] = s2[i]; }
    }
    __syncthreads();

    for (int t = 0; t < TILES_PER_HALF; t++) {
        const size_t rowbase =
            (size_t)(blockIdx.x * (2 * TILES_PER_HALF) + half * TILES_PER_HALF + t) * 64;

        {
            const float4* xg = (const float4*)(x + rowbase * DIM);
#pragma unroll
            for (int ii = 0; ii < 8; ii++) {
                int i = tid_h + ii * 256;
                float4 v = xg[i];
                int row = i >> 5, k = (i & 31) * 4;
                uint32_t off = (uint32_t)((k * 2) ^ ((row & 7) << 4)) + row * 256;
                *(uint2*)(sm + offX + off) =
                    make_uint2(pack_h2(__float2half_rn(v.x), __float2half_rn(v.y)),
                               pack_h2(__float2half_rn(v.z), __float2half_rn(v.w)));
            }
        }
        HBAR(bar);

        float acc[2][8][4];
#pragma unroll
        for (int a = 0; a < 2; a++)
#pragma unroll
            for (int b = 0; b < 8; b++)
#pragma unroll
                for (int c = 0; c < 4; c++) acc[a][b][c] = 0.f;

#pragma unroll
        for (int ks = 0; ks < 8; ks++) {
            const int kb = ks * 32;
            uint32_t aw[2][4];
#pragma unroll
            for (int mt = 0; mt < 2; mt++)
                ldsm4(a_addr(sb + offX, 256, wm * 32 + mt * 16, kb, lane), aw[mt]);
#pragma unroll
            for (int ntp = 0; ntp < 4; ntp++) {
                const int n0 = wn * 64 + ntp * 16;
                uint32_t bw[4];
                ldsm4(b_addr(sb + OFF_W1, 256, n0, kb, lane), bw);
#pragma unroll
                for (int mt = 0; mt < 2; mt++) {
                    mma16816(acc[mt][ntp * 2],     aw[mt], bw[0], bw[1]);
                    mma16816(acc[mt][ntp * 2 + 1], aw[mt], bw[2], bw[3]);
                }
            }
        }

#pragma unroll
        for (int nt = 0; nt < 8; nt++) {
            const int col = wn * 64 + nt * 8 + (lane & 3) * 2;
            const float2 bb = *(const float2*)&b1[col];
#pragma unroll
            for (int mt = 0; mt < 2; mt++) {
                const int r = wm * 32 + mt * 16 + (lane >> 2);
#pragma unroll
                for (int h = 0; h < 2; h++) {
                    const int rr = r + h * 8;
                    float v0 = gelu_fast(acc[mt][nt][h * 2]     + bb.x);
                    float v1 = gelu_fast(acc[mt][nt][h * 2 + 1] + bb.y);
                    uint32_t off = rr * 512 + (uint32_t)((col * 2) ^ ((rr & 7) << 4));
                    *(uint32_t*)(sm + offH1 + off) =
                        pack_h2(__float2half_rn(v0), __float2half_rn(v1));
                }
            }
        }
        HBAR(bar);

        float acc2[2][4][4];
#pragma unroll
        for (int a = 0; a < 2; a++)
#pragma unroll
            for (int b = 0; b < 4; b++)
#pragma unroll
                for (int c = 0; c < 4; c++) acc2[a][b][c] = 0.f;

#pragma unroll
        for (int ks = 0; ks < 16; ks++) {
            const int kb = ks * 32;
            uint32_t aw[2][4];
#pragma unroll
            for (int mt = 0; mt < 2; mt++)
                ldsm4(a_addr(sb + offH1, 512, wm * 32 + mt * 16, kb, lane), aw[mt]);
#pragma unroll
            for (int ntp = 0; ntp < 2; ntp++) {
                const int n0 = wn * 32 + ntp * 16;
                uint32_t bw[4];
                ldsm4(b_addr(sb + OFF_W2, 512, n0, kb, lane), bw);
#pragma unroll
                for (int mt = 0; mt < 2; mt++) {
                    mma16816(acc2[mt][ntp * 2],     aw[mt], bw[0], bw[1]);
                    mma16816(acc2[mt][ntp * 2 + 1], aw[mt], bw[2], bw[3]);
                }
            }
        }

#pragma unroll
        for (int nt = 0; nt < 4; nt++) {
            const int col = wn * 32 + nt * 8 + (lane & 3) * 2;
            const float2 bb = *(const float2*)&b2[col];
#pragma unroll
            for (int mt = 0; mt < 2; mt++) {
                const int r = wm * 32 + mt * 16 + (lane >> 2);
#pragma unroll
                for (int h = 0; h < 2; h++) {
                    const int rr = r + h * 8;
                    *(uint32_t*)&g_hbufh[(rowbase + rr) * DIM + col] =
                        pack_h2(__float2half_rn(acc2[mt][nt][h * 2] + bb.x),
                                __float2half_rn(acc2[mt][nt][h * 2 + 1] + bb.y));
                }
            }
        }
        HBAR(bar);
    }
}

// ---------------------------------------------------------------------------
// K2: scatter-mean v6 = R14's v4 gather with MLP 16.
// ---------------------------------------------------------------------------
#define SPLITS 16
#define WLMAX  96
#define CLMAX  768

__global__ void __launch_bounds__(256)
scatter_gather(const int* __restrict__ hub_idx,
               const int* __restrict__ batch_idx,
               float* __restrict__ hubf_out) {
    __shared__ int wlist[8][4][WLMAX];
    __shared__ int wcnt[8][4];
    __shared__ int clist[4][CLMAX];
    __shared__ int ccnt[4];
    __shared__ int coff[8][4];
    __shared__ int srange[2];

    const int b = blockIdx.x >> 4;
    const int p = blockIdx.x & 15;
    const int h0 = p * 4;
    const int tid = threadIdx.x;
    const int w = tid >> 5;
    const int lane = tid & 31;

    if (lane < 4) wcnt[w][lane] = 0;
    if (tid < 2) {
        int target = b + tid, lo = 0, hi = NS;
        while (lo < hi) { int mid = (lo + hi) >> 1; if (batch_idx[mid] < target) lo = mid + 1; else hi = mid; }
        srange[tid] = lo;
    }
    __syncthreads();

    const int s0 = srange[0];
    const int n = srange[1] - s0;
    const int chunk = (n + 7) >> 3;
    const int cs = s0 + w * chunk;
    const int ce = min(cs + chunk, s0 + n);

    // phase 1: per-warp parallel list build (preserves global ascending order)
    const unsigned lt = (1u << lane) - 1u;
    for (int base = cs; base < ce; base += 32) {
        int i = base + lane;
        int h = (i < ce) ? __ldg(&hub_idx[i]) : -1;
        int hl = h - h0;
        bool in = (hl >= 0) && (hl < 4);
        unsigned mm = __match_any_sync(0xffffffffu, h);
        if (in) {
            int rank = __popc(mm & lt);
            int cnt = __popc(mm);
            int basec = wcnt[w][hl];
            wlist[w][hl][basec + rank] = i;
            if (rank == cnt - 1) wcnt[w][hl] = basec + cnt;
        }
        __syncwarp();
    }
    __syncthreads();

    // phase 2a: prefix offsets
    if (tid < 4) {
        int run = 0;
#pragma unroll
        for (int ww = 0; ww < 8; ww++) { coff[ww][tid] = run; run += wcnt[ww][tid]; }
        ccnt[tid] = run;
    }
    __syncthreads();

    // phase 2b: compact
#pragma unroll
    for (int hl = 0; hl < 4; hl++) {
        int c = wcnt[w][hl], o = coff[w][hl];
        for (int j = lane; j < c; j += 32) clist[hl][o + j] = wlist[w][hl][j];
    }
    __syncthreads();

    // phase 3: gather — thread = (hub, dim-pair), half2 loads, 16 in flight
    {
        const int hl = tid >> 6;           // 0..3 (warp-uniform)
        const int dd = (tid & 63) * 2;     // dim pair
        const int cnt = ccnt[hl];
        const int* lst = clist[hl];
        float sx = 0.f, sy = 0.f;
        int j = 0;
        for (; j + 16 <= cnt; j += 16) {
            __half2 v[16];
#pragma unroll
            for (int q = 0; q < 16; q++)
                v[q] = *(const __half2*)&g_hbufh[(size_t)lst[j + q] * DIM + dd];
#pragma unroll
            for (int q = 0; q < 16; q++) {
                float2 f = __half22float2(v[q]);
                sx += f.x; sy += f.y;
            }
        }
        if (j + 8 <= cnt) {
            __half2 v[8];
#pragma unroll
            for (int q = 0; q < 8; q++)
                v[q] = *(const __half2*)&g_hbufh[(size_t)lst[j + q] * DIM + dd];
#pragma unroll
            for (int q = 0; q < 8; q++) {
                float2 f = __half22float2(v[q]);
                sx += f.x; sy += f.y;
            }
            j += 8;
        }
        for (; j < cnt; j++) {
            float2 f = __half22float2(*(const __half2*)&g_hbufh[(size_t)lst[j] * DIM + dd]);
            sx += f.x; sy += f.y;
        }
        const float inv = 1.0f / (float)max(cnt, 1);
        *(float2*)&hubf_out[((size_t)b * HH + h0 + hl) * DIM + dd] =
            make_float2(sx * inv, sy * inv);
    }
}

// ---------------------------------------------------------------------------
// K3a: kNN, 2 blocks per graph (32 i-rows each) -> g_knn
// ---------------------------------------------------------------------------
__global__ void __launch_bounds__(256)
knn_kernel(const float* __restrict__ hubf) {
    __shared__ float hf[HH][DIM + 1];
    __shared__ float d2row[8][HH];

    const int b = blockIdx.x >> 1;
    const int hp = blockIdx.x & 1;
    const int tid = threadIdx.x;
    const int warp = tid >> 5, lane = tid & 31;

    for (int i = tid; i < HH * DIM; i += 256) {
        int h = i >> 7, d = i & 127;
        hf[h][d] = hubf[((size_t)b * HH + h) * DIM + d];
    }
    __syncthreads();

    for (int i = hp * 32 + warp; i < hp * 32 + 32; i += 8) {
        for (int jj = 0; jj < HH; jj += 32) {
            int j = jj + lane;
            float s = 0.f;
#pragma unroll
            for (int d = 0; d < DIM; d++) {
                float diff = hf[i][d] - hf[j][d];
                s = fmaf(diff, diff, s);
            }
            d2row[warp][j] = s;
        }
        float v0 = d2row[warp][lane], v1 = d2row[warp][lane + 32];
        int   i0 = lane,              i1 = lane + 32;
#pragma unroll
        for (int k = 0; k < KK_; k++) {
            float bv; int bi;
            if (v0 < v1 || (v0 == v1 && i0 < i1)) { bv = v0; bi = i0; }
            else                                   { bv = v1; bi = i1; }
#pragma unroll
            for (int off = 16; off; off >>= 1) {
                float ov = __shfl_xor_sync(0xffffffffu, bv, off);
                int   oi = __shfl_xor_sync(0xffffffffu, bi, off);
                if (ov < bv || (ov == bv && oi < bi)) { bv = ov; bi = oi; }
            }
            if (lane == 0) g_knn[(b * HH + i) * KK_ + k] = bi;
            if (i0 == bi) v0 = 3.4e38f;
            if (i1 == bi) v1 = 3.4e38f;
        }
    }
}

// ---------------------------------------------------------------------------
// K3b: edge emit — 4 spokes per thread, batched loads (MLP 4)
// ---------------------------------------------------------------------------
__global__ void __launch_bounds__(512)
edge_kernel(const int* __restrict__ hub_idx,
            const int* __restrict__ batch_idx,
            float* __restrict__ e0, float* __restrict__ e1) {
    const int base = blockIdx.x * 2048 + threadIdx.x;
    int sb4[4], sh4[4];
#pragma unroll
    for (int k = 0; k < 4; k++) {
        int s = base + k * 512;
        sb4[k] = __ldg(&batch_idx[s]);
        sh4[k] = __ldg(&hub_idx[s]);
    }
    int4 kn4[4];
#pragma unroll
    for (int k = 0; k < 4; k++)
        kn4[k] = *(const int4*)&g_knn[(sb4[k] * HH + sh4[k]) * KK_];
#pragma unroll
    for (int k = 0; k < 4; k++) {
        int s = base + k * 512;
        const float fs = (float)s;
        const float boff = (float)(sb4[k] * HH);
        *(float4*)&e0[(size_t)s * 4] = make_float4(fs, fs, fs, fs);
        *(float4*)&e1[(size_t)s * 4] =
            make_float4(kn4[k].x + boff, kn4[k].y + boff, kn4[k].z + boff, kn4[k].w + boff);
    }
}

// ---------------------------------------------------------------------------
extern "C" void kernel_launch(void* const* d_in, const int* in_sizes, int n_in,
                              void* d_out, int out_size) {
    const float* x   = (const float*)d_in[0];
    const int*   hub = (const int*)d_in[1];
    const int*   bix = (const int*)d_in[2];
    const float* W1  = (const float*)d_in[3];
    const float* b1  = (const float*)d_in[4];
    const float* W2  = (const float*)d_in[5];
    const float* b2  = (const float*)d_in[6];

    float* out  = (float*)d_out;
    float* hubf = out;
    float* e0   = out + HUBF_ELEMS;
    float* e1   = out + HUBF_ELEMS + NK;

    cudaFuncSetAttribute(ffn_mma, cudaFuncAttributeMaxDynamicSharedMemorySize, FFN_SMEM);

    prep_weights<<<64, 256>>>(W1, W2);                     // idx 0
    nudge_kernel<<<1, 32>>>();                              // idx 1
    ffn_mma<<<FFN_GRID, 512, FFN_SMEM>>>(x, b1, b2);       // idx 2
    scatter_gather<<<BG * SPLITS, 256>>>(hub, bix, hubf);  // idx 3 <- ncu
    knn_kernel<<<BG * 2, 256>>>(hubf);
    edge_kernel<<<NS / 2048, 512>>>(hub, bix, e0, e1);
}

// round 17
// speedup vs baseline: 1.0738x; 1.0269x over previous
#include <cuda_runtime.h>
#include <cuda_fp16.h>
#include <cstdint>

#define NS   524288
#define DIM  128
#define BG   128
#define HH   64
#define KK_  4
#define BH   (BG * HH)
#define NK   (NS * KK_)
#define HUBF_ELEMS (BH * DIM)

// hub sums of gelu(h1): [B*H][256] fp32, + counts
__device__ float g_hubsum[(size_t)BH * 256];
__device__ int   g_cnt[BH];
// knn table
__device__ int   g_knn[BH * KK_];

// Prepped fp16 weights, transposed [n][k], XOR-swizzled
__device__ __half gW1[256 * 128];   // [256n][128k], row stride 256B
__device__ __half gW2[128 * 256];   // [128n][256k], row stride 512B

// ffn1 SMEM layout
#define OFF_W1   0          /* 64KB */
#define OFF_X    65536      /* [128][128] fp16 sw, 32KB */
#define OFF_H1   98304      /* [128][256] fp16 sw, 64KB */
#define OFF_ACC  163840     /* [64][256] fp32, 64KB */
#define OFF_MISC 229376     /* shub[128] + scnt[64] + srange[2] ints */
#define FFN_SMEM (229376 + 1024)

// hub_gemm SMEM: W2 64KB + H [128][256] fp16 64KB
#define HG_OFF_W2 0
#define HG_OFF_H  65536
#define HG_SMEM   131072

// ---------------------------------------------------------------------------
__device__ __forceinline__ uint32_t smem_u32(const void* p) {
    uint32_t a;
    asm("{ .reg .u64 t; cvta.to.shared.u64 t, %1; cvt.u32.u64 %0, t; }" : "=r"(a) : "l"(p));
    return a;
}
__device__ __forceinline__ void ldsm4(uint32_t addr, uint32_t r[4]) {
    asm volatile("ldmatrix.sync.aligned.m8n8.x4.shared.b16 {%0,%1,%2,%3}, [%4];"
                 : "=r"(r[0]), "=r"(r[1]), "=r"(r[2]), "=r"(r[3]) : "r"(addr));
}
__device__ __forceinline__ void mma16816(float c[4], const uint32_t a[4], uint32_t b0, uint32_t b1) {
    asm volatile("mma.sync.aligned.m16n8k16.row.col.f32.f16.f16.f32 "
                 "{%0,%1,%2,%3}, {%4,%5,%6,%7}, {%8,%9}, {%0,%1,%2,%3};"
                 : "+f"(c[0]), "+f"(c[1]), "+f"(c[2]), "+f"(c[3])
                 : "r"(a[0]), "r"(a[1]), "r"(a[2]), "r"(a[3]), "r"(b0), "r"(b1));
}
__device__ __forceinline__ uint32_t a_addr(uint32_t base, int stride, int m0, int kb, int lane) {
    int row = m0 + (lane & 15);
    int k = kb + ((lane >> 4) << 4);
    return base + row * stride + (uint32_t)(k ^ ((row & 7) << 4));
}
__device__ __forceinline__ uint32_t b_addr(uint32_t base, int stride, int n0, int kb, int lane) {
    int row = n0 + (lane & 7) + ((lane & 16) >> 1);
    int k = kb + (((lane >> 3) & 1) << 4);
    return base + row * stride + (uint32_t)(k ^ ((row & 7) << 4));
}
__device__ __forceinline__ float gelu_fast(float v) {
    float c = v * fmaf(v * v, 0.044715f, 1.0f) * 0.7978845608f;
    float t;
    asm("tanh.approx.f32 %0, %1;" : "=f"(t) : "f"(c));
    return 0.5f * v * (1.0f + t);
}
__device__ __forceinline__ uint32_t pack_h2(__half a, __half b) {
    __half2 t; t.x = a; t.y = b;
    return *(uint32_t*)&t;
}

// ---------------------------------------------------------------------------
// K0: weight prep — fp16 quantize + transpose + XOR swizzle
// ---------------------------------------------------------------------------
__global__ void prep_weights(const float* __restrict__ W1, const float* __restrict__ W2) {
    int tid = threadIdx.x + blockIdx.x * blockDim.x;
    int stride = blockDim.x * gridDim.x;
    for (int i = tid; i < 32768; i += stride) {
        int n = i >> 7, k = i & 127;
        uint32_t off = (uint32_t)(n * 256) + (uint32_t)((k * 2) ^ ((n & 7) << 4));
        *(__half*)((char*)gW1 + off) = __float2half_rn(W1[k * 256 + n]);
    }
    for (int i = tid; i < 32768; i += stride) {
        int n = i >> 8, k = i & 255;
        uint32_t off = (uint32_t)(n * 512) + (uint32_t)((k * 2) ^ ((n & 7) << 4));
        *(__half*)((char*)gW2 + off) = __float2half_rn(W2[k * 128 + n]);
    }
}

__global__ void nudge_kernel() {}

// ---------------------------------------------------------------------------
// K1: ffn1 — one CTA per graph. Per 128-row tile: GEMM1 + GELU -> h1 (fp16
// smem), then column-owned fp32 accumulation into per-graph ACC[64][256]
// (deterministic: fixed tile order, serial rows, exclusive column ownership).
// Writes g_hubsum + g_cnt. GEMM2 deferred to hub_gemm (linearity).
// ---------------------------------------------------------------------------
__global__ void __launch_bounds__(512)
ffn1(const float* __restrict__ x,
     const int* __restrict__ hub_idx,
     const int* __restrict__ batch_idx,
     const float* __restrict__ b1) {
    extern __shared__ char sm[];
    const uint32_t sb = smem_u32(sm);
    float* ACC = (float*)(sm + OFF_ACC);
    int* shub = (int*)(sm + OFF_MISC);
    int* scnt = shub + 128;
    int* srange = scnt + 64;

    const int g = blockIdx.x;
    const int tid = threadIdx.x;
    const int wid = tid >> 5;
    const int lane = tid & 31;
    const int wm = wid & 3;       // 4 m-warps (32 rows each)
    const int wn = wid >> 2;      // 4 n-warps (64 cols each)

    // W1 resident + zero ACC + counts + graph range
    {
        const uint4* s1 = (const uint4*)gW1;
        uint4* d1 = (uint4*)(sm + OFF_W1);
#pragma unroll 4
        for (int i = tid; i < 4096; i += 512) d1[i] = s1[i];
    }
    for (int i = tid; i < 64 * 256; i += 512) ACC[i] = 0.f;
    if (tid < 64) scnt[tid] = 0;
    if (tid < 2) {
        int target = g + tid, lo = 0, hi = NS;
        while (lo < hi) { int mid = (lo + hi) >> 1; if (batch_idx[mid] < target) lo = mid + 1; else hi = mid; }
        srange[tid] = lo;
    }
    __syncthreads();

    const int s0 = srange[0], s1r = srange[1];
    const int ntiles = (s1r - s0 + 127) >> 7;

    for (int t = 0; t < ntiles; t++) {
        const int rbase = s0 + t * 128;
        const int nrows = min(128, s1r - rbase);

        // ---- load x tile (guarded) -> fp16 X smem; load hub ids ----
        {
            const float4* xg = (const float4*)x;
#pragma unroll
            for (int ii = 0; ii < 8; ii++) {
                int i = tid + ii * 512;
                int row = i >> 5, k = (i & 31) * 4;
                float4 v = (row < nrows) ? xg[(size_t)(rbase + row) * 32 + (i & 31)]
                                         : make_float4(0.f, 0.f, 0.f, 0.f);
                uint32_t off = (uint32_t)((k * 2) ^ ((row & 7) << 4)) + row * 256;
                *(uint2*)(sm + OFF_X + off) =
                    make_uint2(pack_h2(__float2half_rn(v.x), __float2half_rn(v.y)),
                               pack_h2(__float2half_rn(v.z), __float2half_rn(v.w)));
            }
            if (tid < 128) shub[tid] = (tid < nrows) ? __ldg(&hub_idx[rbase + tid]) : 0;
            if (tid >= 128 && tid < 256 && (tid - 128) < nrows)
                atomicAdd(&scnt[__ldg(&hub_idx[rbase + tid - 128])], 0); // warm nothing
        }
        __syncthreads();

        // counts (integer atomics -> deterministic)
        if (tid < 128 && tid < nrows) atomicAdd(&scnt[shub[tid]], 1);

        // ---- GEMM1: [128,128] x [128,256], warp tile 32x64 ----
        float acc[2][8][4];
#pragma unroll
        for (int a = 0; a < 2; a++)
#pragma unroll
            for (int b = 0; b < 8; b++)
#pragma unroll
                for (int c = 0; c < 4; c++) acc[a][b][c] = 0.f;

#pragma unroll
        for (int ks = 0; ks < 8; ks++) {
            const int kb = ks * 32;
            uint32_t aw[2][4];
#pragma unroll
            for (int mt = 0; mt < 2; mt++)
                ldsm4(a_addr(sb + OFF_X, 256, wm * 32 + mt * 16, kb, lane), aw[mt]);
#pragma unroll
            for (int ntp = 0; ntp < 4; ntp++) {
                const int n0 = wn * 64 + ntp * 16;
                uint32_t bw[4];
                ldsm4(b_addr(sb + OFF_W1, 256, n0, kb, lane), bw);
#pragma unroll
                for (int mt = 0; mt < 2; mt++) {
                    mma16816(acc[mt][ntp * 2],     aw[mt], bw[0], bw[1]);
                    mma16816(acc[mt][ntp * 2 + 1], aw[mt], bw[2], bw[3]);
                }
            }
        }

        // ---- Epilogue: +b1, GELU, fp16 -> H1 smem ----
#pragma unroll
        for (int nt = 0; nt < 8; nt++) {
            const int col = wn * 64 + nt * 8 + (lane & 3) * 2;
            const float2 bb = *(const float2*)&b1[col];
#pragma unroll
            for (int mt = 0; mt < 2; mt++) {
                const int r = wm * 32 + mt * 16 + (lane >> 2);
#pragma unroll
                for (int h = 0; h < 2; h++) {
                    const int rr = r + h * 8;
                    float v0 = gelu_fast(acc[mt][nt][h * 2]     + bb.x);
                    float v1 = gelu_fast(acc[mt][nt][h * 2 + 1] + bb.y);
                    uint32_t off = rr * 512 + (uint32_t)((col * 2) ^ ((rr & 7) << 4));
                    *(uint32_t*)(sm + OFF_H1 + off) = pack_h2(__float2half_rn(v0), __float2half_rn(v1));
                }
            }
        }
        __syncthreads();

        // ---- column-owned accumulation: thread=col, serial rows ----
        if (tid < 256) {
            const int c = tid;
            float* accc = ACC + c;
            int r = 0;
            for (; r + 4 <= nrows; r += 4) {
                int h0v = shub[r], h1v = shub[r + 1], h2v = shub[r + 2], h3v = shub[r + 3];
                float v0 = __half2float(*(__half*)(sm + OFF_H1 + (r)     * 512 + (uint32_t)((c * 2) ^ (((r)     & 7) << 4))));
                float v1 = __half2float(*(__half*)(sm + OFF_H1 + (r + 1) * 512 + (uint32_t)((c * 2) ^ (((r + 1) & 7) << 4))));
                float v2 = __half2float(*(__half*)(sm + OFF_H1 + (r + 2) * 512 + (uint32_t)((c * 2) ^ (((r + 2) & 7) << 4))));
                float v3 = __half2float(*(__half*)(sm + OFF_H1 + (r + 3) * 512 + (uint32_t)((c * 2) ^ (((r + 3) & 7) << 4))));
                accc[h0v * 256] += v0;
                accc[h1v * 256] += v1;
                accc[h2v * 256] += v2;
                accc[h3v * 256] += v3;
            }
            for (; r < nrows; r++) {
                float v = __half2float(*(__half*)(sm + OFF_H1 + r * 512 + (uint32_t)((c * 2) ^ ((r & 7) << 4))));
                accc[shub[r] * 256] += v;
            }
        }
        __syncthreads();   // ACC/H1/X reads done before next tile
    }

    // write hubsum + counts
    float* dst = g_hubsum + (size_t)g * (HH * 256);
    for (int i = tid; i < 64 * 256; i += 512) dst[i] = ACC[i];
    if (tid < 64) g_cnt[g * HH + tid] = scnt[tid];
}

// ---------------------------------------------------------------------------
// K2: hub_gemm — hubf = (hubsum/cnt) @ W2 + b2.  8192 rows, 64 CTAs x 128 rows.
// ---------------------------------------------------------------------------
__global__ void __launch_bounds__(512)
hub_gemm(const float* __restrict__ b2, float* __restrict__ hubf_out) {
    extern __shared__ char sm[];
    const uint32_t sb = smem_u32(sm);
    const int tid = threadIdx.x;
    const int wid = tid >> 5;
    const int lane = tid & 31;
    const int wm = wid & 3;
    const int wn = wid >> 2;
    const int rowbase = blockIdx.x * 128;

    // W2 resident
    {
        const uint4* s2 = (const uint4*)gW2;
        uint4* d2 = (uint4*)(sm + HG_OFF_W2);
#pragma unroll 4
        for (int i = tid; i < 4096; i += 512) d2[i] = s2[i];
    }
    // load hub means -> fp16 H smem (swizzled). 128 rows x 256 cols; float2 per thread
    {
#pragma unroll
        for (int ii = 0; ii < 32; ii++) {
            int i = tid + ii * 512;          // 16384 col-pairs
            int row = i >> 7, cp = (i & 127) * 2;
            float inv = 1.0f / (float)max(__ldg(&g_cnt[rowbase + row]), 1);
            float2 v = *(const float2*)&g_hubsum[(size_t)(rowbase + row) * 256 + cp];
            uint32_t off = row * 512 + (uint32_t)((cp * 2) ^ ((row & 7) << 4));
            *(uint32_t*)(sm + HG_OFF_H + off) =
                pack_h2(__float2half_rn(v.x * inv), __float2half_rn(v.y * inv));
        }
    }
    __syncthreads();

    // GEMM2: [128,256] x [256,128], warp tile 32x32
    float acc2[2][4][4];
#pragma unroll
    for (int a = 0; a < 2; a++)
#pragma unroll
        for (int b = 0; b < 4; b++)
#pragma unroll
            for (int c = 0; c < 4; c++) acc2[a][b][c] = 0.f;

#pragma unroll
    for (int ks = 0; ks < 16; ks++) {
        const int kb = ks * 32;
        uint32_t aw[2][4];
#pragma unroll
        for (int mt = 0; mt < 2; mt++)
            ldsm4(a_addr(sb + HG_OFF_H, 512, wm * 32 + mt * 16, kb, lane), aw[mt]);
#pragma unroll
        for (int ntp = 0; ntp < 2; ntp++) {
            const int n0 = wn * 32 + ntp * 16;
            uint32_t bw[4];
            ldsm4(b_addr(sb + HG_OFF_W2, 512, n0, kb, lane), bw);
#pragma unroll
            for (int mt = 0; mt < 2; mt++) {
                mma16816(acc2[mt][ntp * 2],     aw[mt], bw[0], bw[1]);
                mma16816(acc2[mt][ntp * 2 + 1], aw[mt], bw[2], bw[3]);
            }
        }
    }

    // +b2 -> hubf
#pragma unroll
    for (int nt = 0; nt < 4; nt++) {
        const int col = wn * 32 + nt * 8 + (lane & 3) * 2;
        const float2 bb = *(const float2*)&b2[col];
#pragma unroll
        for (int mt = 0; mt < 2; mt++) {
            const int r = wm * 32 + mt * 16 + (lane >> 2);
#pragma unroll
            for (int h = 0; h < 2; h++) {
                const int rr = r + h * 8;
                float2 v = make_float2(acc2[mt][nt][h * 2] + bb.x,
                                       acc2[mt][nt][h * 2 + 1] + bb.y);
                *(float2*)&hubf_out[(size_t)(rowbase + rr) * DIM + col] = v;
            }
        }
    }
}

// ---------------------------------------------------------------------------
// K3a: kNN, 2 blocks per graph -> g_knn
// ---------------------------------------------------------------------------
__global__ void __launch_bounds__(256)
knn_kernel(const float* __restrict__ hubf) {
    __shared__ float hf[HH][DIM + 1];
    __shared__ float d2row[8][HH];

    const int b = blockIdx.x >> 1;
    const int hp = blockIdx.x & 1;
    const int tid = threadIdx.x;
    const int warp = tid >> 5, lane = tid & 31;

    for (int i = tid; i < HH * DIM; i += 256) {
        int h = i >> 7, d = i & 127;
        hf[h][d] = hubf[((size_t)b * HH + h) * DIM + d];
    }
    __syncthreads();

    for (int i = hp * 32 + warp; i < hp * 32 + 32; i += 8) {
        for (int jj = 0; jj < HH; jj += 32) {
            int j = jj + lane;
            float s = 0.f;
#pragma unroll
            for (int d = 0; d < DIM; d++) {
                float diff = hf[i][d] - hf[j][d];
                s = fmaf(diff, diff, s);
            }
            d2row[warp][j] = s;
        }
        float v0 = d2row[warp][lane], v1 = d2row[warp][lane + 32];
        int   i0 = lane,              i1 = lane + 32;
#pragma unroll
        for (int k = 0; k < KK_; k++) {
            float bv; int bi;
            if (v0 < v1 || (v0 == v1 && i0 < i1)) { bv = v0; bi = i0; }
            else                                   { bv = v1; bi = i1; }
#pragma unroll
            for (int off = 16; off; off >>= 1) {
                float ov = __shfl_xor_sync(0xffffffffu, bv, off);
                int   oi = __shfl_xor_sync(0xffffffffu, bi, off);
                if (ov < bv || (ov == bv && oi < bi)) { bv = ov; bi = oi; }
            }
            if (lane == 0) g_knn[(b * HH + i) * KK_ + k] = bi;
            if (i0 == bi) v0 = 3.4e38f;
            if (i1 == bi) v1 = 3.4e38f;
        }
    }
}

// ---------------------------------------------------------------------------
// K3b: edge emit — 4 spokes per thread
// ---------------------------------------------------------------------------
__global__ void __launch_bounds__(512)
edge_kernel(const int* __restrict__ hub_idx,
            const int* __restrict__ batch_idx,
            float* __restrict__ e0, float* __restrict__ e1) {
    const int base = blockIdx.x * 2048 + threadIdx.x;
    int sb4[4], sh4[4];
#pragma unroll
    for (int k = 0; k < 4; k++) {
        int s = base + k * 512;
        sb4[k] = __ldg(&batch_idx[s]);
        sh4[k] = __ldg(&hub_idx[s]);
    }
    int4 kn4[4];
#pragma unroll
    for (int k = 0; k < 4; k++)
        kn4[k] = *(const int4*)&g_knn[(sb4[k] * HH + sh4[k]) * KK_];
#pragma unroll
    for (int k = 0; k < 4; k++) {
        int s = base + k * 512;
        const float fs = (float)s;
        const float boff = (float)(sb4[k] * HH);
        *(float4*)&e0[(size_t)s * 4] = make_float4(fs, fs, fs, fs);
        *(float4*)&e1[(size_t)s * 4] =
            make_float4(kn4[k].x + boff, kn4[k].y + boff, kn4[k].z + boff, kn4[k].w + boff);
    }
}

// ---------------------------------------------------------------------------
extern "C" void kernel_launch(void* const* d_in, const int* in_sizes, int n_in,
                              void* d_out, int out_size) {
    const float* x   = (const float*)d_in[0];
    const int*   hub = (const int*)d_in[1];
    const int*   bix = (const int*)d_in[2];
    const float* W1  = (const float*)d_in[3];
    const float* b1  = (const float*)d_in[4];
    const float* W2  = (const float*)d_in[5];
    const float* b2  = (const float*)d_in[6];

    float* out  = (float*)d_out;
    float* hubf = out;
    float* e0   = out + HUBF_ELEMS;
    float* e1   = out + HUBF_ELEMS + NK;

    cudaFuncSetAttribute(ffn1, cudaFuncAttributeMaxDynamicSharedMemorySize, FFN_SMEM);
    cudaFuncSetAttribute(hub_gemm, cudaFuncAttributeMaxDynamicSharedMemorySize, HG_SMEM);

    prep_weights<<<64, 256>>>(W1, W2);                 // idx 0
    nudge_kernel<<<1, 32>>>();                          // idx 1
    nudge_kernel<<<1, 32>>>();                          // idx 2
    ffn1<<<BG, 512, FFN_SMEM>>>(x, hub, bix, b1);      // idx 3 <- ncu
    hub_gemm<<<BH / 128, 512, HG_SMEM>>>(b2, hubf);
    knn_kernel<<<BG * 2, 256>>>(hubf);
    edge_kernel<<<NS / 2048, 512>>>(hub, bix, e0, e1);
}